// round 1
// baseline (speedup 1.0000x reference)
#include <cuda_runtime.h>
#include <math.h>

#define NB 16
#define NC 64
#define IMG 256
#define PLANE 65536
#define NWIN 64

// scratch (device globals — no allocation allowed)
__device__ float g_y[NB * NWIN * NC];      // [b][n][c] pooled tokens
__device__ float g_dist[NB * NWIN * NWIN]; // [b][n][m] softmax attention

__device__ __forceinline__ void fma2(unsigned long long& d,
                                     unsigned long long a,
                                     unsigned long long b) {
    asm("fma.rn.f32x2 %0, %1, %2, %0;" : "+l"(d) : "l"(a), "l"(b));
}

// ---------------------------------------------------------------------------
// Kernel A: adaptive avg pool 8x8 — one CTA per (b,c) plane, coalesced reads.
// ---------------------------------------------------------------------------
__global__ __launch_bounds__(256) void pool_kernel(const float* __restrict__ x) {
    int bc = blockIdx.x;
    const float* plane = x + (size_t)bc * PLANE;
    int t = threadIdx.x;
    int warp = t >> 5, lane = t & 31;

    __shared__ float wsum[64];
    if (t < 64) wsum[t] = 0.f;
    __syncthreads();

    for (int pass = 0; pass < 32; pass++) {
        int row = pass * 8 + warp;
        const float4* rp = (const float4*)(plane + row * IMG);
        float4 v1 = rp[lane];
        float4 v2 = rp[lane + 32];
        float s1 = v1.x + v1.y + v1.z + v1.w;
        float s2 = v2.x + v2.y + v2.z + v2.w;
        // reduce within 8-lane groups (one window-column each)
        s1 += __shfl_xor_sync(~0u, s1, 4);
        s1 += __shfl_xor_sync(~0u, s1, 2);
        s1 += __shfl_xor_sync(~0u, s1, 1);
        s2 += __shfl_xor_sync(~0u, s2, 4);
        s2 += __shfl_xor_sync(~0u, s2, 2);
        s2 += __shfl_xor_sync(~0u, s2, 1);
        if ((lane & 7) == 0) {
            int wr = row >> 5;
            atomicAdd(&wsum[wr * 8 + (lane >> 3)], s1);
            atomicAdd(&wsum[wr * 8 + (lane >> 3) + 4], s2);
        }
    }
    __syncthreads();
    if (t < 64) {
        int b = bc >> 6, c = bc & 63;
        g_y[((size_t)b * NWIN + t) * NC + c] = wsum[t] * (1.0f / 1024.0f);
    }
}

// ---------------------------------------------------------------------------
// Kernel B: q = yWq^T, k = yWk^T, dist = softmax(q k^T / 8). One CTA per batch.
// ---------------------------------------------------------------------------
__global__ __launch_bounds__(256) void dist_kernel(const float* __restrict__ Wq,
                                                   const float* __restrict__ Wk) {
    __shared__ float sY[4096];  // y[n][c], later scores[n][m]
    __shared__ float sA[4096];  // Wq[k][c], later q[n][k]
    __shared__ float sB2[4096]; // Wk[k][c], later k[n][k]
    int b = blockIdx.x, t = threadIdx.x;

    for (int idx = t; idx < 4096; idx += 256) {
        sY[idx]  = g_y[b * 4096 + idx];
        sA[idx]  = Wq[idx];
        sB2[idx] = Wk[idx];
    }
    __syncthreads();

    int n = t >> 2;
    int kk = (t & 3) * 16;

    float qv[16], kv[16];
    #pragma unroll
    for (int e = 0; e < 16; e++) {
        float aq = 0.f, ak = 0.f;
        const float* yr = &sY[n * 64];
        const float* wq = &sA[(kk + e) * 64];
        const float* wk = &sB2[(kk + e) * 64];
        #pragma unroll
        for (int c = 0; c < 64; c++) {
            aq = fmaf(yr[c], wq[c], aq);
            ak = fmaf(yr[c], wk[c], ak);
        }
        qv[e] = aq; kv[e] = ak;
    }
    __syncthreads();
    #pragma unroll
    for (int e = 0; e < 16; e++) {
        sA[n * 64 + kk + e]  = qv[e];
        sB2[n * 64 + kk + e] = kv[e];
    }
    __syncthreads();

    float sv[16];
    #pragma unroll
    for (int e = 0; e < 16; e++) {
        int m = kk + e;
        float s = 0.f;
        const float* qr = &sA[n * 64];
        const float* kr = &sB2[m * 64];
        #pragma unroll
        for (int k = 0; k < 64; k++) s = fmaf(qr[k], kr[k], s);
        sv[e] = s * 0.125f;  // 1/sqrt(64)
    }
    __syncthreads();
    #pragma unroll
    for (int e = 0; e < 16; e++) sY[n * 64 + kk + e] = sv[e];
    __syncthreads();

    // softmax: 8 warps x 8 rows, 2 elems/lane
    int warp = t >> 5, lane = t & 31;
    for (int j = 0; j < 8; j++) {
        int row = warp * 8 + j;
        float a  = sY[row * 64 + lane];
        float c2 = sY[row * 64 + lane + 32];
        float mx = fmaxf(a, c2);
        for (int d = 16; d >= 1; d >>= 1) mx = fmaxf(mx, __shfl_xor_sync(~0u, mx, d));
        float ea = expf(a - mx), eb = expf(c2 - mx);
        float s = ea + eb;
        for (int d = 16; d >= 1; d >>= 1) s += __shfl_xor_sync(~0u, s, d);
        float inv = 1.0f / s;
        g_dist[b * 4096 + row * 64 + lane]      = ea * inv;
        g_dist[b * 4096 + row * 64 + lane + 32] = eb * inv;
    }
}

// ---------------------------------------------------------------------------
// Kernel C: att. CTA = (b, c, ig): 8 i-rows x all 64 windows of one plane.
// OUT[(r,i)][(pc,j)] = sum_{mr,mc} D[r*8+pc][mr*8+mc] * X[(mr,i)][(mc,j)]
// Packed f32x2 math (FFMA2): 2x fp32 FMA throughput vs scalar FFMA.
// smem: sD = dist duplicated into f32x2 pairs, rows padded to 65 (bank-safe);
//       sX = 64 image rows x 128 float2.
// ---------------------------------------------------------------------------
__global__ void __launch_bounds__(256, 2) att_kernel(const float* __restrict__ x,
                                                     float* __restrict__ out) {
    extern __shared__ unsigned long long smem[];
    unsigned long long* sD = smem;          // 64*65 u64 = 33280 B
    unsigned long long* sX = smem + 4160;   // 8192 u64  = 65536 B

    int blk = blockIdx.x;
    int ig = blk & 3;
    int bc = blk >> 2;
    int b = bc >> 6;
    int t = threadIdx.x;
    int i   = t >> 5;          // warp id = local image-row within group of 8
    int jq  = t & 31;
    int pc  = jq >> 2;         // window column (0..7)
    int j2b = (jq & 3) * 4;    // float2-column base within window (0..12)

    // dist -> smem, duplicated (w,w) as u64, layout sD[m*65 + n]
    const float* dptr = g_dist + b * 4096;
    for (int idx = t; idx < 4096; idx += 256) {
        int n = idx >> 6, m = idx & 63;
        unsigned long long w = (unsigned long long)__float_as_uint(dptr[idx]);
        w |= w << 32;
        sD[m * 65 + n] = w;
    }
    // X tile: rows mr*32 + ig*8 + il for mr,il in 0..7
    const float* plane = x + (size_t)bc * PLANE;
    float4* sX4 = (float4*)sX;
    for (int idx = t; idx < 4096; idx += 256) {
        int rl = idx >> 6, quad = idx & 63;
        int imrow = (rl >> 3) * 32 + ig * 8 + (rl & 7);
        sX4[rl * 64 + quad] = ((const float4*)(plane + imrow * IMG))[quad];
    }
    __syncthreads();

    unsigned long long acc[8][4];
    #pragma unroll
    for (int r = 0; r < 8; r++) {
        acc[r][0] = 0ull; acc[r][1] = 0ull; acc[r][2] = 0ull; acc[r][3] = 0ull;
    }

    for (int mr = 0; mr < 8; mr++) {
        const unsigned long long* xr = sX + mr * 1024 + i * 128 + j2b;
        const unsigned long long* dr = sD + (mr * 8) * 65 + pc;
        #pragma unroll
        for (int mc = 0; mc < 8; mc++) {
            ulonglong2 xa = *(const ulonglong2*)(xr + mc * 16);
            ulonglong2 xb = *(const ulonglong2*)(xr + mc * 16 + 2);
            const unsigned long long* dm = dr + mc * 65;
            #pragma unroll
            for (int r = 0; r < 8; r++) {
                unsigned long long w = dm[r * 8];
                fma2(acc[r][0], w, xa.x);
                fma2(acc[r][1], w, xa.y);
                fma2(acc[r][2], w, xb.x);
                fma2(acc[r][3], w, xb.y);
            }
        }
    }

    float* outp = out + (size_t)bc * PLANE;
    #pragma unroll
    for (int r = 0; r < 8; r++) {
        int imrow = r * 32 + ig * 8 + i;
        ulonglong2* po = (ulonglong2*)((unsigned long long*)(outp + imrow * IMG) + jq * 4);
        po[0] = make_ulonglong2(acc[r][0], acc[r][1]);
        po[1] = make_ulonglong2(acc[r][2], acc[r][3]);
    }
}

extern "C" void kernel_launch(void* const* d_in, const int* in_sizes, int n_in,
                              void* d_out, int out_size) {
    const float* x  = (const float*)d_in[0];
    const float* Wq = (const float*)d_in[1];
    const float* Wk = (const float*)d_in[2];
    float* out = (float*)d_out;

    cudaFuncSetAttribute(att_kernel, cudaFuncAttributeMaxDynamicSharedMemorySize, 98816);

    pool_kernel<<<NB * NC, 256>>>(x);
    dist_kernel<<<NB, 256>>>(Wq, Wk);
    att_kernel<<<NB * NC * 4, 256, 98816>>>(x, out);
}

// round 3
// speedup vs baseline: 1.8631x; 1.8631x over previous
#include <cuda_runtime.h>
#include <cuda_bf16.h>
#include <cstdint>
#include <math.h>

#define NB 16
#define NC 64
#define IMG 256
#define PLANE 65536

// scratch (device globals — no allocation allowed)
__device__ float g_y[NB * 64 * NC];      // [b][n][c] pooled tokens
__device__ float g_dist[NB * 64 * 64];   // [b][n][m] softmax attention

// ---------------------------------------------------------------------------
// Kernel A: adaptive avg pool 8x8 — one CTA per (b,c) plane, coalesced reads.
// ---------------------------------------------------------------------------
__global__ __launch_bounds__(256) void pool_kernel(const float* __restrict__ x) {
    int bc = blockIdx.x;
    const float* plane = x + (size_t)bc * PLANE;
    int t = threadIdx.x;
    int warp = t >> 5, lane = t & 31;

    __shared__ float wsum[64];
    if (t < 64) wsum[t] = 0.f;
    __syncthreads();

    for (int pass = 0; pass < 32; pass++) {
        int row = pass * 8 + warp;
        const float4* rp = (const float4*)(plane + row * IMG);
        float4 v1 = rp[lane];
        float4 v2 = rp[lane + 32];
        float s1 = v1.x + v1.y + v1.z + v1.w;
        float s2 = v2.x + v2.y + v2.z + v2.w;
        s1 += __shfl_xor_sync(~0u, s1, 4);
        s1 += __shfl_xor_sync(~0u, s1, 2);
        s1 += __shfl_xor_sync(~0u, s1, 1);
        s2 += __shfl_xor_sync(~0u, s2, 4);
        s2 += __shfl_xor_sync(~0u, s2, 2);
        s2 += __shfl_xor_sync(~0u, s2, 1);
        if ((lane & 7) == 0) {
            int wr = row >> 5;
            atomicAdd(&wsum[wr * 8 + (lane >> 3)], s1);
            atomicAdd(&wsum[wr * 8 + (lane >> 3) + 4], s2);
        }
    }
    __syncthreads();
    if (t < 64) {
        int b = bc >> 6, c = bc & 63;
        g_y[((size_t)b * 64 + t) * NC + c] = wsum[t] * (1.0f / 1024.0f);
    }
}

// ---------------------------------------------------------------------------
// Kernel B: q = yWq^T, k = yWk^T, dist = softmax(q k^T / 8). One CTA per batch.
// ---------------------------------------------------------------------------
__global__ __launch_bounds__(256) void dist_kernel(const float* __restrict__ Wq,
                                                   const float* __restrict__ Wk) {
    __shared__ float sY[4096];
    __shared__ float sA[4096];
    __shared__ float sB2[4096];
    int b = blockIdx.x, t = threadIdx.x;

    for (int idx = t; idx < 4096; idx += 256) {
        sY[idx]  = g_y[b * 4096 + idx];
        sA[idx]  = Wq[idx];
        sB2[idx] = Wk[idx];
    }
    __syncthreads();

    int n = t >> 2;
    int kk = (t & 3) * 16;

    float qv[16], kv[16];
    #pragma unroll
    for (int e = 0; e < 16; e++) {
        float aq = 0.f, ak = 0.f;
        const float* yr = &sY[n * 64];
        const float* wq = &sA[(kk + e) * 64];
        const float* wk = &sB2[(kk + e) * 64];
        #pragma unroll
        for (int c = 0; c < 64; c++) {
            aq = fmaf(yr[c], wq[c], aq);
            ak = fmaf(yr[c], wk[c], ak);
        }
        qv[e] = aq; kv[e] = ak;
    }
    __syncthreads();
    #pragma unroll
    for (int e = 0; e < 16; e++) {
        sA[n * 64 + kk + e]  = qv[e];
        sB2[n * 64 + kk + e] = kv[e];
    }
    __syncthreads();

    float sv[16];
    #pragma unroll
    for (int e = 0; e < 16; e++) {
        int m = kk + e;
        float s = 0.f;
        const float* qr = &sA[n * 64];
        const float* kr = &sB2[m * 64];
        #pragma unroll
        for (int k = 0; k < 64; k++) s = fmaf(qr[k], kr[k], s);
        sv[e] = s * 0.125f;
    }
    __syncthreads();
    #pragma unroll
    for (int e = 0; e < 16; e++) sY[n * 64 + kk + e] = sv[e];
    __syncthreads();

    int warp = t >> 5, lane = t & 31;
    for (int j = 0; j < 8; j++) {
        int row = warp * 8 + j;
        float a  = sY[row * 64 + lane];
        float c2 = sY[row * 64 + lane + 32];
        float mx = fmaxf(a, c2);
        for (int d = 16; d >= 1; d >>= 1) mx = fmaxf(mx, __shfl_xor_sync(~0u, mx, d));
        float ea = expf(a - mx), eb = expf(c2 - mx);
        float s = ea + eb;
        for (int d = 16; d >= 1; d >>= 1) s += __shfl_xor_sync(~0u, s, d);
        float inv = 1.0f / s;
        g_dist[b * 4096 + row * 64 + lane]      = ea * inv;
        g_dist[b * 4096 + row * 64 + lane + 32] = eb * inv;
    }
}

// ---------------------------------------------------------------------------
// Kernel C (att): mma.sync bf16 hi/lo-split GEMM (legacy HMMA path — the
// tcgen05 path doesn't compile under this harness's compute_103 PTX target).
// CTA = (b, c, ig). OUT[64 n][256 px] = dist[64x64] @ V[64x256], where
// V[m=(mr,mc)][px=(il,jc)] = x[b,c, mr*32+ig*8+il, mc*32+jc].
// A (dist) bf16 hi/lo in smem (144B rows); B (V) bf16 hi/lo k-major (528B rows).
// 3 passes: Ah*Bh + Ah*Bl + Al*Bh into fp32 acc.
// Warp w = image row il=w: M=64 x N=32 -> 4x4 tiles of m16n8.
// ---------------------------------------------------------------------------
#define SM_BH 0
#define SM_BL 33792
#define SM_AH 67584
#define SM_AL 76800
#define SMEM_ATT 86016

__device__ __forceinline__ uint32_t smem_u32(const void* p) {
    uint32_t a;
    asm("{ .reg .u64 t; cvta.to.shared.u64 t, %1; cvt.u32.u64 %0, t; }"
        : "=r"(a) : "l"(p));
    return a;
}
__device__ __forceinline__ uint32_t pack_bf16(float lo, float hi) {
    uint32_t r;
    asm("cvt.rn.bf16x2.f32 %0, %1, %2;" : "=r"(r) : "f"(hi), "f"(lo));
    return r;
}

__global__ void __launch_bounds__(256, 2) att_kernel(const float* __restrict__ x,
                                                     float* __restrict__ out) {
    extern __shared__ char sm[];
    uint32_t sbase = smem_u32(sm);
    int t = threadIdx.x;
    int wid = t >> 5, lane = t & 31;

    int blk = blockIdx.x;
    int ig = blk & 3;
    int c  = (blk >> 2) & 63;
    int b  = blk >> 8;

    const float* xplane = x + (size_t)(b * 64 + c) * PLANE;

    // ---- B build: 64 source image rows; warp w builds rows sr = w*8..w*8+7 ----
    #pragma unroll
    for (int it = 0; it < 8; it++) {
        int sr = wid * 8 + it;
        int mr = sr >> 3, il = sr & 7;
        const float4* xr = (const float4*)(xplane + (size_t)(mr * 32 + ig * 8 + il) * IMG);
        #pragma unroll
        for (int rep = 0; rep < 2; rep++) {
            int l2 = lane + rep * 32;
            float4 v = xr[l2];
            uint32_t h01 = pack_bf16(v.x, v.y);
            uint32_t h23 = pack_bf16(v.z, v.w);
            float lx = v.x - __uint_as_float(h01 << 16);
            float ly = v.y - __uint_as_float(h01 & 0xffff0000u);
            float lz = v.z - __uint_as_float(h23 << 16);
            float lw = v.w - __uint_as_float(h23 & 0xffff0000u);
            uint32_t l01 = pack_bf16(lx, ly);
            uint32_t l23 = pack_bf16(lz, lw);
            int mc = l2 >> 3, jc0 = (l2 & 7) * 4;
            uint32_t off = (uint32_t)(mr * 8 + mc) * 528u + (uint32_t)(il * 32 + jc0) * 2u;
            *(uint2*)(sm + SM_BH + off) = make_uint2(h01, h23);
            *(uint2*)(sm + SM_BL + off) = make_uint2(l01, l23);
        }
    }

    // ---- A build: dist hi/lo -> smem. Thread t: row t>>2, 16 cols at (t&3)*16 ----
    {
        int row = t >> 2, q = (t & 3) * 16;
        const float4* dr = (const float4*)(g_dist + b * 4096 + row * 64 + q);
        uint32_t hv[8], lv[8];
        #pragma unroll
        for (int i = 0; i < 4; i++) {
            float4 dv = dr[i];
            uint32_t h0 = pack_bf16(dv.x, dv.y);
            uint32_t h1 = pack_bf16(dv.z, dv.w);
            float lx = dv.x - __uint_as_float(h0 << 16);
            float ly = dv.y - __uint_as_float(h0 & 0xffff0000u);
            float lz = dv.z - __uint_as_float(h1 << 16);
            float lw = dv.w - __uint_as_float(h1 & 0xffff0000u);
            hv[2*i] = h0; hv[2*i+1] = h1;
            lv[2*i] = pack_bf16(lx, ly); lv[2*i+1] = pack_bf16(lz, lw);
        }
        uint32_t off = (uint32_t)row * 144u + (uint32_t)q * 2u;
        *(uint4*)(sm + SM_AH + off)      = make_uint4(hv[0], hv[1], hv[2], hv[3]);
        *(uint4*)(sm + SM_AH + off + 16) = make_uint4(hv[4], hv[5], hv[6], hv[7]);
        *(uint4*)(sm + SM_AL + off)      = make_uint4(lv[0], lv[1], lv[2], lv[3]);
        *(uint4*)(sm + SM_AL + off + 16) = make_uint4(lv[4], lv[5], lv[6], lv[7]);
    }
    __syncthreads();

    // ---- MMA mainloop ----
    float acc[4][4][4];
    #pragma unroll
    for (int mt = 0; mt < 4; mt++)
        #pragma unroll
        for (int nt = 0; nt < 4; nt++) {
            acc[mt][nt][0] = 0.f; acc[mt][nt][1] = 0.f;
            acc[mt][nt][2] = 0.f; acc[mt][nt][3] = 0.f;
        }

    // ldmatrix lane addressing
    int row16 = lane & 15;
    uint32_t a_lane_off = (uint32_t)row16 * 144u + (uint32_t)((lane >> 4) * 8) * 2u;
    uint32_t b_lane_off = (uint32_t)row16 * 528u + (uint32_t)(wid * 32) * 2u;

    const uint32_t aBase[3] = { sbase + SM_AH, sbase + SM_AH, sbase + SM_AL };
    const uint32_t bBase[3] = { sbase + SM_BH, sbase + SM_BL, sbase + SM_BH };

    #pragma unroll
    for (int s = 0; s < 3; s++) {
        uint32_t aB = aBase[s] + a_lane_off;
        uint32_t bB = bBase[s] + b_lane_off;
        #pragma unroll
        for (int kk = 0; kk < 4; kk++) {
            // B fragments for 4 n-tiles (16 k x 8 n each), k-major smem + trans
            uint32_t bf[4][2];
            #pragma unroll
            for (int nt = 0; nt < 4; nt++) {
                uint32_t addr = bB + (uint32_t)(kk * 16) * 528u + (uint32_t)(nt * 8) * 2u;
                asm volatile("ldmatrix.sync.aligned.m8n8.x2.trans.shared.b16 {%0,%1}, [%2];"
                             : "=r"(bf[nt][0]), "=r"(bf[nt][1]) : "r"(addr));
            }
            #pragma unroll
            for (int mt = 0; mt < 4; mt++) {
                uint32_t af[4];
                uint32_t addr = aB + (uint32_t)(mt * 16) * 144u + (uint32_t)(kk * 16) * 2u;
                asm volatile("ldmatrix.sync.aligned.m8n8.x4.shared.b16 {%0,%1,%2,%3}, [%4];"
                             : "=r"(af[0]), "=r"(af[1]), "=r"(af[2]), "=r"(af[3]) : "r"(addr));
                #pragma unroll
                for (int nt = 0; nt < 4; nt++) {
                    asm volatile(
                        "mma.sync.aligned.m16n8k16.row.col.f32.bf16.bf16.f32 "
                        "{%0,%1,%2,%3}, {%4,%5,%6,%7}, {%8,%9}, {%0,%1,%2,%3};"
                        : "+f"(acc[mt][nt][0]), "+f"(acc[mt][nt][1]),
                          "+f"(acc[mt][nt][2]), "+f"(acc[mt][nt][3])
                        : "r"(af[0]), "r"(af[1]), "r"(af[2]), "r"(af[3]),
                          "r"(bf[nt][0]), "r"(bf[nt][1]));
                }
            }
        }
    }

    // ---- epilogue: acc -> out ----
    {
        int g = lane >> 2, tig = lane & 3;
        float* oplane = out + (size_t)(b * 64 + c) * PLANE;
        int rowbase = ig * 8 + wid;  // il = wid
        #pragma unroll
        for (int mt = 0; mt < 4; mt++) {
            #pragma unroll
            for (int nt = 0; nt < 4; nt++) {
                int jc = nt * 8 + tig * 2;
                int n1 = mt * 16 + g;
                int n2 = n1 + 8;
                float* p1 = oplane + (size_t)((n1 >> 3) * 32 + rowbase) * IMG
                          + (n1 & 7) * 32 + jc;
                float* p2 = oplane + (size_t)((n2 >> 3) * 32 + rowbase) * IMG
                          + (n2 & 7) * 32 + jc;
                *(float2*)p1 = make_float2(acc[mt][nt][0], acc[mt][nt][1]);
                *(float2*)p2 = make_float2(acc[mt][nt][2], acc[mt][nt][3]);
            }
        }
    }
}

extern "C" void kernel_launch(void* const* d_in, const int* in_sizes, int n_in,
                              void* d_out, int out_size) {
    const float* x  = (const float*)d_in[0];
    const float* Wq = (const float*)d_in[1];
    const float* Wk = (const float*)d_in[2];
    float* out = (float*)d_out;

    cudaFuncSetAttribute(att_kernel, cudaFuncAttributeMaxDynamicSharedMemorySize, SMEM_ATT);

    pool_kernel<<<NB * NC, 256>>>(x);
    dist_kernel<<<NB, 256>>>(Wq, Wk);
    att_kernel<<<NB * NC * 4, 256, SMEM_ATT>>>(x, out);
}